// round 14
// baseline (speedup 1.0000x reference)
#include <cuda_runtime.h>

#define NNODES_C 10000
#define NEDGES_C 160000
typedef unsigned long long u64;

__device__ float g_nodeftr[NNODES_C * 20];   // zero at load; node_kernel re-zeroes after use
__device__ float g_tmp[NEDGES_C * 20];

static __device__ __forceinline__ u64 pack2(float x) {
    u64 r;
    asm("mov.b64 %0, {%1, %1};" : "=l"(r) : "r"(__float_as_uint(x)));
    return r;
}
static __device__ __forceinline__ float2 unpack2(u64 v) {
    float lo, hi;
    asm("mov.b64 {%0, %1}, %2;" : "=f"(lo), "=f"(hi) : "l"(v));
    return make_float2(lo, hi);
}
static __device__ __forceinline__ u64 fma2(u64 a, u64 b, u64 c) {
    u64 d;
    asm("fma.rn.f32x2 %0, %1, %2, %3;" : "=l"(d) : "l"(a), "l"(b), "l"(c));
    return d;
}
static __device__ __forceinline__ void red4(float* p, float a, float b, float c, float d) {
    asm volatile("red.global.add.v4.f32 [%0], {%1, %2, %3, %4};"
                 :: "l"(p), "f"(a), "f"(b), "f"(c), "f"(d) : "memory");
}

// tp1 smem (floats): [0,160) W1 | [160,9376) W2 | scratch 4608 u64 (36/thread, warp-blocked)
#define TP1_SMEM_FLOATS (160 + 9216 + 9216)

// ============================ Kernel A: MLP1 + TP1 + gating (2 edges/thread, dieted) ============================
__global__ __launch_bounds__(128, 3) void edge_tp1_kernel(
    const float* __restrict__ hn, const float* __restrict__ he,
    const int* __restrict__ esrc, const int* __restrict__ edst,
    const float* __restrict__ evec, const float* __restrict__ emb,
    const float* __restrict__ fcW1, const float* __restrict__ fcW2, int E)
{
    const float SQ3f    = 1.7320508075688772f;
    const float INVSQ3f = 0.57735026918962576f;
    const float RS10    = 0.31622776601683794f;
    const float CS1     = 0.14433756729740645f;   // 1/sqrt(48)
    const float CV1     = 0.20412414523193150f;   // 1/sqrt(24)

    extern __shared__ __align__(16) float smem[];
    float* sW1 = smem;
    float* sW2 = smem + 160;
    u64*   scrU = (u64*)(smem + 9376);

    {
        const float4* g1 = (const float4*)fcW1;
        float4* d1 = (float4*)sW1;
        for (int t = threadIdx.x; t < 40; t += 128) {
            float4 a = g1[t]; d1[t] = make_float4(a.x*RS10, a.y*RS10, a.z*RS10, a.w*RS10);
        }
        const float4* g2 = (const float4*)fcW2;
        float4* d2 = (float4*)sW2;
        const float sS = CS1 * 0.25f, sV = CV1 * 0.25f;
        for (int t = threadIdx.x; t < 2304; t += 128) {
            int c0 = (t*4) % 576;
            float sc = (c0 < 288) ? sS : (c0 < 432) ? sV : (c0 < 528) ? sS : sV;
            float4 a = g2[t]; d2[t] = make_float4(a.x*sc, a.y*sc, a.z*sc, a.w*sc);
        }
    }
    __syncthreads();

    int tid  = threadIdx.x;
    int warp = tid >> 5;
    int lane = tid & 31;
    int base = blockIdx.x * 256;
    int e0 = base + tid;
    if (e0 >= E) return;
    int e1 = base + 128 + tid;
    bool v1 = (e1 < E);
    int e1c = v1 ? e1 : e0;

    // per-thread scratch: slot s -> myU[s*32]; float half j -> ((float*)(myU+s*32))[j]
    u64* myU = scrU + (size_t)warp*36*32 + lane;

    const ulonglong2* W2 = (const ulonglong2*)sW2;   // 144 chunks per k-row

    float h1f[2][16];
    u64 a1p[2][2][3];

    // ---- per-edge prologue: gather (s,dots -> scratch pairs), MLP1, vv ----
#pragma unroll
    for (int j = 0; j < 2; j++) {
        int e = j ? e1c : e0;
        int srcI = esrc[e], dstI = edst[e];
        float vf[36];
        {
            float4 r0[5], r1[5], r2[5];
            const float4* p = (const float4*)(he + (size_t)e*20);
#pragma unroll
            for (int i = 0; i < 5; i++) r0[i] = p[i];
            const float4* ps = (const float4*)(hn + (size_t)srcI*20);
#pragma unroll
            for (int i = 0; i < 5; i++) r1[i] = ps[i];
            const float4* pd = (const float4*)(hn + (size_t)dstI*20);
#pragma unroll
            for (int i = 0; i < 5; i++) r2[i] = pd[i];
            const float* re = (const float*)r0;
            const float* rs = (const float*)r1;
            const float* rd = (const float*)r2;
#pragma unroll
            for (int q = 0; q < 8; q++) {
                ((float*)(myU + (q     )*32))[j] = re[q];
                ((float*)(myU + (8 + q )*32))[j] = rs[q];
                ((float*)(myU + (16 + q)*32))[j] = rd[q];
            }
#pragma unroll
            for (int q = 0; q < 12; q++) { vf[q] = re[8+q]; vf[12+q] = rs[8+q]; vf[24+q] = rd[8+q]; }
        }
        float sh0, sh1v, sh2;
        {
            float ex = evec[e*3+0], ey = evec[e*3+1], ez = evec[e*3+2];
            float nn = sqrtf(ex*ex + ey*ey + ez*ez) + 1e-12f;
            float f = SQ3f / nn;
            sh0 = ex*f; sh1v = ey*f; sh2 = ez*f;
        }
#pragma unroll
        for (int i = 0; i < 12; i++)
            ((float*)(myU + (24 + i)*32))[j] =
                (vf[i*3+0]*sh0 + vf[i*3+1]*sh1v + vf[i*3+2]*sh2) * INVSQ3f;

        // MLP1 -> h1f[j] (floats)
        {
            float embr[10];
            const float2* pe2 = (const float2*)(emb + (size_t)e*10);
#pragma unroll
            for (int q = 0; q < 5; q++) { float2 t = pe2[q]; embr[2*q] = t.x; embr[2*q+1] = t.y; }
            const ulonglong2* W = (const ulonglong2*)sW1;
            u64 acc[8];
#pragma unroll
            for (int p = 0; p < 8; p++) acc[p] = 0ull;
#pragma unroll
            for (int q = 0; q < 10; q++) {
                u64 ej = pack2(embr[q]);
#pragma unroll
                for (int g = 0; g < 4; g++) {
                    ulonglong2 w = W[q*4+g];
                    acc[2*g]   = fma2(ej, w.x, acc[2*g]);
                    acc[2*g+1] = fma2(ej, w.y, acc[2*g+1]);
                }
            }
#pragma unroll
            for (int p = 0; p < 8; p++) {
                float2 f = unpack2(acc[p]);
                h1f[j][2*p]   = fmaxf(f.x, 0.f);
                h1f[j][2*p+1] = fmaxf(f.y, 0.f);
            }
        }

        // vv: chunk 132 + i (unrolled; consumes vf while register-resident)
#pragma unroll
        for (int c = 0; c < 3; c++) { a1p[j][0][c] = 0ull; a1p[j][1][c] = 0ull; }
#pragma unroll
        for (int i = 0; i < 12; i++) {
            u64 aA = 0ull, aB = 0ull;
#pragma unroll
            for (int k = 0; k < 16; k++) {
                u64 hk = pack2(h1f[j][k]);
                ulonglong2 w = W2[k*144 + 132 + i];
                aA = fma2(hk, w.x, aA);
                aB = fma2(hk, w.y, aB);
            }
#pragma unroll
            for (int c = 0; c < 3; c++) {
                u64 vc2 = pack2(vf[i*3+c]);
                a1p[j][0][c] = fma2(vc2, aA, a1p[j][0][c]);
                a1p[j][1][c] = fma2(vc2, aB, a1p[j][1][c]);
            }
        }
    }

    // merged out0 accumulators (vs first, ss adds on top)
    u64 a0p[2][6];
#pragma unroll
    for (int p = 0; p < 6; p++) { a0p[0][p] = 0ull; a0p[1][p] = 0ull; }

    // ---- vs: chunk 72 + i*3 + g (dots pair from scratch; weights shared by both edges) ----
#pragma unroll 1
    for (int i = 0; i < 12; i++) {
        float2 df = unpack2(myU[(24 + i)*32]);
        u64 d0 = pack2(df.x);
        u64 d1 = pack2(df.y);
        const ulonglong2* Wb = W2 + 72 + i*3;
#pragma unroll
        for (int g = 0; g < 3; g++) {
            u64 aA0 = 0ull, aB0 = 0ull, aA1 = 0ull, aB1 = 0ull;
#pragma unroll
            for (int k = 0; k < 16; k++) {
                u64 hk0 = pack2(h1f[0][k]);
                u64 hk1 = pack2(h1f[1][k]);
                ulonglong2 w = Wb[k*144 + g];
                aA0 = fma2(hk0, w.x, aA0);
                aB0 = fma2(hk0, w.y, aB0);
                aA1 = fma2(hk1, w.x, aA1);
                aB1 = fma2(hk1, w.y, aB1);
            }
            a0p[0][2*g]   = fma2(d0, aA0, a0p[0][2*g]);
            a0p[0][2*g+1] = fma2(d0, aB0, a0p[0][2*g+1]);
            a0p[1][2*g]   = fma2(d1, aA1, a0p[1][2*g]);
            a0p[1][2*g+1] = fma2(d1, aB1, a0p[1][2*g+1]);
        }
    }

    // ---- ss: chunk i*3 + g (s pair from scratch) ----
#pragma unroll 1
    for (int i = 0; i < 24; i++) {
        float2 sf = unpack2(myU[i*32]);
        u64 s0 = pack2(sf.x);
        u64 s1 = pack2(sf.y);
        const ulonglong2* Wb = W2 + i*3;
#pragma unroll
        for (int g = 0; g < 3; g++) {
            u64 aA0 = 0ull, aB0 = 0ull, aA1 = 0ull, aB1 = 0ull;
#pragma unroll
            for (int k = 0; k < 16; k++) {
                u64 hk0 = pack2(h1f[0][k]);
                u64 hk1 = pack2(h1f[1][k]);
                ulonglong2 w = Wb[k*144 + g];
                aA0 = fma2(hk0, w.x, aA0);
                aB0 = fma2(hk0, w.y, aB0);
                aA1 = fma2(hk1, w.x, aA1);
                aB1 = fma2(hk1, w.y, aB1);
            }
            a0p[0][2*g]   = fma2(s0, aA0, a0p[0][2*g]);
            a0p[0][2*g+1] = fma2(s0, aB0, a0p[0][2*g+1]);
            a0p[1][2*g]   = fma2(s1, aA1, a0p[1][2*g]);
            a0p[1][2*g+1] = fma2(s1, aB1, a0p[1][2*g+1]);
        }
    }

    // ---- sv: chunk 108 + i ----
    u64 asvp[2][2];
    asvp[0][0] = 0ull; asvp[0][1] = 0ull; asvp[1][0] = 0ull; asvp[1][1] = 0ull;
#pragma unroll 1
    for (int i = 0; i < 24; i++) {
        u64 aA0 = 0ull, aB0 = 0ull, aA1 = 0ull, aB1 = 0ull;
        const ulonglong2* Wb = W2 + 108 + i;
#pragma unroll
        for (int k = 0; k < 16; k++) {
            u64 hk0 = pack2(h1f[0][k]);
            u64 hk1 = pack2(h1f[1][k]);
            ulonglong2 w = Wb[k*144];
            aA0 = fma2(hk0, w.x, aA0);
            aB0 = fma2(hk0, w.y, aB0);
            aA1 = fma2(hk1, w.x, aA1);
            aB1 = fma2(hk1, w.y, aB1);
        }
        float2 sf = unpack2(myU[i*32]);
        u64 s0 = pack2(sf.x);
        u64 s1 = pack2(sf.y);
        asvp[0][0] = fma2(s0, aA0, asvp[0][0]);
        asvp[0][1] = fma2(s0, aB0, asvp[0][1]);
        asvp[1][0] = fma2(s1, aA1, asvp[1][0]);
        asvp[1][1] = fma2(s1, aB1, asvp[1][1]);
    }

    // ---- gating -> g_tmp (scales folded into weights); sh1 recomputed from evec ----
#pragma unroll
    for (int j = 0; j < 2; j++) {
        if (j == 1 && !v1) break;
        int e = j ? e1 : e0;
        float sh[3];
        {
            float ex = evec[e*3+0], ey = evec[e*3+1], ez = evec[e*3+2];
            float nn = sqrtf(ex*ex + ey*ey + ez*ez) + 1e-12f;
            float f = SQ3f / nn;
            sh[0] = ex*f; sh[1] = ey*f; sh[2] = ez*f;
        }
        float outr[20];
        float a0[12], asv[4], a1[4][3];
#pragma unroll
        for (int p = 0; p < 6; p++) {
            float2 f = unpack2(a0p[j][p]);
            a0[2*p] = f.x; a0[2*p+1] = f.y;
        }
        {
            float2 f0 = unpack2(asvp[j][0]); float2 f1 = unpack2(asvp[j][1]);
            asv[0] = f0.x; asv[1] = f0.y; asv[2] = f1.x; asv[3] = f1.y;
        }
#pragma unroll
        for (int c = 0; c < 3; c++) {
            float2 f0 = unpack2(a1p[j][0][c]); float2 f1 = unpack2(a1p[j][1][c]);
            a1[0][c] = f0.x; a1[1][c] = f0.y; a1[2][c] = f1.x; a1[3][c] = f1.y;
        }
#pragma unroll
        for (int o = 0; o < 8; o++) outr[o] = fmaxf(a0[o], 0.f);
#pragma unroll
        for (int o = 0; o < 4; o++) {
            float gate = fmaxf(a0[8+o], 0.f);
#pragma unroll
            for (int c = 0; c < 3; c++)
                outr[8 + o*3 + c] = (asv[o]*sh[c] + a1[o][c]) * gate;
        }
        float4* tp = (float4*)(g_tmp + (size_t)e*20);
        const float4* sp = (const float4*)outr;
#pragma unroll
        for (int t = 0; t < 5; t++) tp[t] = sp[t];
    }
}

// ============================ Kernel B: MLP2 + TP2 + epilogue (fully unrolled) ============================
__global__ __launch_bounds__(128, 4) void edge_tp2_kernel(
    const float* __restrict__ he,
    const int* __restrict__ edst, const float* __restrict__ evec,
    const float* __restrict__ emb, const float* __restrict__ enorm,
    const float* __restrict__ fc2W1, const float* __restrict__ fc2W2,
    float* __restrict__ out_he, int E)
{
    const float SQ3f    = 1.7320508075688772f;
    const float INVSQ3f = 0.57735026918962576f;
    const float RS10    = 0.31622776601683794f;
    const float CS2     = 0.25f;
    const float CV2     = 0.35355339059327379f;

    __shared__ __align__(16) float sW1b[160];
    __shared__ __align__(16) float sW2b[2304];
    {
        const float4* g1b = (const float4*)fc2W1;
        float4* d1b = (float4*)sW1b;
        for (int t = threadIdx.x; t < 40; t += 128) {
            float4 b = g1b[t]; d1b[t] = make_float4(b.x*RS10, b.y*RS10, b.z*RS10, b.w*RS10);
        }
        const float4* g2b = (const float4*)fc2W2;
        float4* d2b = (float4*)sW2b;
        const float sS = CS2 * 0.25f, sV = CV2 * 0.25f;
        for (int t = threadIdx.x; t < 576; t += 128) {
            int c0 = (t*4) % 144;
            float sc = (c0 < 64) ? sS : (c0 < 96) ? sV : (c0 < 128) ? sS : sV;
            float4 a = g2b[t]; d2b[t] = make_float4(a.x*sc, a.y*sc, a.z*sc, a.w*sc);
        }
    }
    __syncthreads();

    int e = blockIdx.x*128 + threadIdx.x;
    if (e >= E) return;

    float ts[8], tv[12];
    {
        float4 r[5];
        const float4* tp = (const float4*)(g_tmp + (size_t)e*20);
#pragma unroll
        for (int i = 0; i < 5; i++) r[i] = tp[i];
        const float* f = (const float*)r;
#pragma unroll
        for (int j = 0; j < 8; j++) ts[j] = f[j];
#pragma unroll
        for (int j = 0; j < 12; j++) tv[j] = f[8+j];
    }

    float sh1[3];
    {
        float ex = evec[e*3+0], ey = evec[e*3+1], ez = evec[e*3+2];
        float nn = sqrtf(ex*ex + ey*ey + ez*ez) + 1e-12f;
        float f = SQ3f / nn;
        sh1[0] = ex*f; sh1[1] = ey*f; sh1[2] = ez*f;
    }
    float dt[4];
#pragma unroll
    for (int i = 0; i < 4; i++)
        dt[i] = (tv[i*3+0]*sh1[0] + tv[i*3+1]*sh1[1] + tv[i*3+2]*sh1[2]) * INVSQ3f;

    u64 h2p[16];
    {
        float embr[10];
        const float2* pe2 = (const float2*)(emb + (size_t)e*10);
#pragma unroll
        for (int j = 0; j < 5; j++) { float2 t = pe2[j]; embr[2*j] = t.x; embr[2*j+1] = t.y; }
        const ulonglong2* W = (const ulonglong2*)sW1b;
        u64 acc[8];
#pragma unroll
        for (int p = 0; p < 8; p++) acc[p] = 0ull;
#pragma unroll
        for (int j = 0; j < 10; j++) {
            u64 ej = pack2(embr[j]);
#pragma unroll
            for (int g = 0; g < 4; g++) {
                ulonglong2 w = W[j*4+g];
                acc[2*g]   = fma2(ej, w.x, acc[2*g]);
                acc[2*g+1] = fma2(ej, w.y, acc[2*g+1]);
            }
        }
#pragma unroll
        for (int p = 0; p < 8; p++) {
            float2 f = unpack2(acc[p]);
            h2p[2*p]   = pack2(fmaxf(f.x, 0.f));
            h2p[2*p+1] = pack2(fmaxf(f.y, 0.f));
        }
    }

    const ulonglong2* W2b = (const ulonglong2*)sW2b;  // 36 chunks per k-row
    u64 b0p[4], bsvp[2], b1p[2][3];
#pragma unroll
    for (int p = 0; p < 4; p++) b0p[p] = 0ull;
    bsvp[0] = 0ull; bsvp[1] = 0ull;
#pragma unroll
    for (int c = 0; c < 3; c++) { b1p[0][c] = 0ull; b1p[1][c] = 0ull; }

    // ss: chunk i*2 + g
#pragma unroll
    for (int i = 0; i < 8; i++) {
        u64 si2 = pack2(ts[i]);
#pragma unroll
        for (int g = 0; g < 2; g++) {
            u64 aA = 0ull, aB = 0ull;
#pragma unroll
            for (int k = 0; k < 16; k++) {
                ulonglong2 w = W2b[k*36 + i*2 + g];
                aA = fma2(h2p[k], w.x, aA);
                aB = fma2(h2p[k], w.y, aB);
            }
            b0p[2*g]   = fma2(si2, aA, b0p[2*g]);
            b0p[2*g+1] = fma2(si2, aB, b0p[2*g+1]);
        }
    }
    // vs: chunk 16 + i*2 + g
#pragma unroll
    for (int i = 0; i < 4; i++) {
        u64 di2 = pack2(dt[i]);
#pragma unroll
        for (int g = 0; g < 2; g++) {
            u64 aA = 0ull, aB = 0ull;
#pragma unroll
            for (int k = 0; k < 16; k++) {
                ulonglong2 w = W2b[k*36 + 16 + i*2 + g];
                aA = fma2(h2p[k], w.x, aA);
                aB = fma2(h2p[k], w.y, aB);
            }
            b0p[2*g]   = fma2(di2, aA, b0p[2*g]);
            b0p[2*g+1] = fma2(di2, aB, b0p[2*g+1]);
        }
    }
    // sv: chunk 24 + i
#pragma unroll
    for (int i = 0; i < 8; i++) {
        u64 aA = 0ull, aB = 0ull;
#pragma unroll
        for (int k = 0; k < 16; k++) {
            ulonglong2 w = W2b[k*36 + 24 + i];
            aA = fma2(h2p[k], w.x, aA);
            aB = fma2(h2p[k], w.y, aB);
        }
        u64 si2 = pack2(ts[i]);
        bsvp[0] = fma2(si2, aA, bsvp[0]);
        bsvp[1] = fma2(si2, aB, bsvp[1]);
    }
    // vv: chunk 32 + i
#pragma unroll
    for (int i = 0; i < 4; i++) {
        u64 aA = 0ull, aB = 0ull;
#pragma unroll
        for (int k = 0; k < 16; k++) {
            ulonglong2 w = W2b[k*36 + 32 + i];
            aA = fma2(h2p[k], w.x, aA);
            aB = fma2(h2p[k], w.y, aB);
        }
#pragma unroll
        for (int c = 0; c < 3; c++) {
            u64 vc2 = pack2(tv[i*3+c]);
            b1p[0][c] = fma2(vc2, aA, b1p[0][c]);
            b1p[1][c] = fma2(vc2, aB, b1p[1][c]);
        }
    }

    float b0[8], bsv[4], b1[4][3];
#pragma unroll
    for (int p = 0; p < 4; p++) {
        float2 f = unpack2(b0p[p]);
        b0[2*p] = f.x; b0[2*p+1] = f.y;
    }
    {
        float2 f0 = unpack2(bsvp[0]); float2 f1 = unpack2(bsvp[1]);
        bsv[0] = f0.x; bsv[1] = f0.y; bsv[2] = f1.x; bsv[3] = f1.y;
    }
#pragma unroll
    for (int c = 0; c < 3; c++) {
        float2 f0 = unpack2(b1p[0][c]); float2 f1 = unpack2(b1p[1][c]);
        b1[0][c] = f0.x; b1[1][c] = f0.y; b1[2][c] = f1.x; b1[3][c] = f1.y;
    }

    float hnew[20];
    {
        float4 r[5];
        const float4* p = (const float4*)(he + (size_t)e*20);
#pragma unroll
        for (int i = 0; i < 5; i++) r[i] = p[i];
        const float* re = (const float*)r;
#pragma unroll
        for (int j = 0; j < 8; j++) hnew[j] = re[j] + b0[j];
#pragma unroll
        for (int o = 0; o < 4; o++)
#pragma unroll
            for (int c = 0; c < 3; c++)
                hnew[8 + o*3 + c] = re[8+o*3+c] + (bsv[o]*sh1[c] + b1[o][c]);
    }

    {
        float4* op = (float4*)(out_he + (size_t)e*20);
        const float4* hp = (const float4*)hnew;
#pragma unroll
        for (int t = 0; t < 5; t++) op[t] = hp[t];
    }
    int dstI = edst[e];
    float nw = enorm[e];
    float* nf = &g_nodeftr[(size_t)dstI*20];
#pragma unroll
    for (int t = 0; t < 5; t++)
        red4(nf + t*4, hnew[t*4]*nw, hnew[t*4+1]*nw, hnew[t*4+2]*nw, hnew[t*4+3]*nw);
}

// ============================ node kernel (also re-zeroes g_nodeftr) ============================
__global__ __launch_bounds__(32) void node_kernel(
    const float* __restrict__ hn,
    const float* __restrict__ WgS, const float* __restrict__ WgV,
    const float* __restrict__ WoS, const float* __restrict__ WoV,
    float* __restrict__ out_hn, int N)
{
    const float RS8 = 0.35355339059327379f;
    int n = blockIdx.x*32 + threadIdx.x;
    if (n >= N) return;

    float cs[16], cv[8][3];
    const float* ph = hn + (size_t)n*20;
    float* pf = g_nodeftr + (size_t)n*20;
#pragma unroll
    for (int j = 0; j < 8; j++) { cs[j] = ph[j]; cs[8+j] = pf[j]; }
#pragma unroll
    for (int i = 0; i < 4; i++)
#pragma unroll
        for (int c = 0; c < 3; c++) { cv[i][c] = ph[8+i*3+c]; cv[4+i][c] = pf[8+i*3+c]; }

    {
        float4 z4 = make_float4(0.f, 0.f, 0.f, 0.f);
        float4* pz = (float4*)pf;
#pragma unroll
        for (int t = 0; t < 5; t++) pz[t] = z4;
    }

    float gl[12];
#pragma unroll
    for (int o = 0; o < 12; o++) {
        float a = 0.f;
#pragma unroll
        for (int i = 0; i < 16; i++) a = fmaf(cs[i], __ldg(&WgS[i*12+o]), a);
        gl[o] = a * 0.25f;
    }
    float vl[4][3];
#pragma unroll
    for (int o = 0; o < 4; o++)
#pragma unroll
        for (int c = 0; c < 3; c++) {
            float a = 0.f;
#pragma unroll
            for (int i = 0; i < 8; i++) a = fmaf(cv[i][c], __ldg(&WgV[i*4+o]), a);
            vl[o][c] = a * RS8;
        }

    float ls[8], lg[4];
#pragma unroll
    for (int j = 0; j < 8; j++) ls[j] = fmaxf(gl[j], 0.f);
#pragma unroll
    for (int o = 0; o < 4; o++) lg[o] = fmaxf(gl[8+o], 0.f);

    float lv[4][3];
#pragma unroll
    for (int o = 0; o < 4; o++)
#pragma unroll
        for (int c = 0; c < 3; c++) lv[o][c] = vl[o][c] * lg[o];

    float os_[8];
#pragma unroll
    for (int o = 0; o < 8; o++) {
        float a = 0.f;
#pragma unroll
        for (int i = 0; i < 8; i++) a = fmaf(ls[i], __ldg(&WoS[i*8+o]), a);
        os_[o] = a * RS8;
    }
    float ov[4][3];
#pragma unroll
    for (int o = 0; o < 4; o++)
#pragma unroll
        for (int c = 0; c < 3; c++) {
            float a = 0.f;
#pragma unroll
            for (int i = 0; i < 4; i++) a = fmaf(lv[i][c], __ldg(&WoV[i*4+o]), a);
            ov[o][c] = a * 0.5f;
        }

    float* po = out_hn + (size_t)n*20;
#pragma unroll
    for (int j = 0; j < 8; j++) po[j] = ph[j] + os_[j];
#pragma unroll
    for (int o = 0; o < 4; o++)
#pragma unroll
        for (int c = 0; c < 3; c++) po[8+o*3+c] = ph[8+o*3+c] + ov[o][c];
}

extern "C" void kernel_launch(void* const* d_in, const int* in_sizes, int n_in,
                              void* d_out, int out_size) {
    const float* hn    = (const float*)d_in[0];
    const float* he    = (const float*)d_in[1];
    const int*   esrc  = (const int*)d_in[2];
    const int*   edst  = (const int*)d_in[3];
    const float* evec  = (const float*)d_in[4];
    const float* emb   = (const float*)d_in[5];
    const float* enorm = (const float*)d_in[6];
    const float* fcW1  = (const float*)d_in[8];
    const float* fcW2  = (const float*)d_in[9];
    const float* fc2W1 = (const float*)d_in[10];
    const float* fc2W2 = (const float*)d_in[11];
    const float* WgS   = (const float*)d_in[12];
    const float* WgV   = (const float*)d_in[13];
    const float* WoS   = (const float*)d_in[14];
    const float* WoV   = (const float*)d_in[15];

    int N = in_sizes[0] / 20;
    int E = in_sizes[1] / 20;

    float* out    = (float*)d_out;
    float* out_hn = out;                      // (N,20) first
    float* out_he = out + (size_t)N * 20;     // (E,20) second

    size_t tp1_smem = TP1_SMEM_FLOATS * sizeof(float);
    cudaFuncSetAttribute(edge_tp1_kernel,
                         cudaFuncAttributeMaxDynamicSharedMemorySize, (int)tp1_smem);

    edge_tp1_kernel<<<(E + 255)/256, 128, tp1_smem>>>(hn, he, esrc, edst, evec, emb, fcW1, fcW2, E);
    edge_tp2_kernel<<<(E + 127)/128, 128>>>(he, edst, evec, emb, enorm, fc2W1, fc2W2, out_he, E);
    node_kernel<<<(N + 31)/32, 32>>>(hn, WgS, WgV, WoS, WoV, out_hn, N);
}

// round 15
// speedup vs baseline: 1.5266x; 1.5266x over previous
#include <cuda_runtime.h>

#define NNODES_C 10000
#define NEDGES_C 160000
typedef unsigned long long u64;

__device__ float g_nodeftr[NNODES_C * 20];   // zero at load; node_kernel re-zeroes after use
__device__ float g_tmp[NEDGES_C * 20];
__device__ float g_mid[NEDGES_C * 40];       // per edge: h1[16] | vs-partial[12] | vv-partial[12]

static __device__ __forceinline__ u64 pack2(float x) {
    u64 r;
    asm("mov.b64 %0, {%1, %1};" : "=l"(r) : "r"(__float_as_uint(x)));
    return r;
}
static __device__ __forceinline__ float2 unpack2(u64 v) {
    float lo, hi;
    asm("mov.b64 {%0, %1}, %2;" : "=f"(lo), "=f"(hi) : "l"(v));
    return make_float2(lo, hi);
}
static __device__ __forceinline__ u64 fma2(u64 a, u64 b, u64 c) {
    u64 d;
    asm("fma.rn.f32x2 %0, %1, %2, %3;" : "=l"(d) : "l"(a), "l"(b), "l"(c));
    return d;
}
static __device__ __forceinline__ void red4(float* p, float a, float b, float c, float d) {
    asm volatile("red.global.add.v4.f32 [%0], {%1, %2, %3, %4};"
                 :: "l"(p), "f"(a), "f"(b), "f"(c), "f"(d) : "memory");
}

// ============================ Kernel A1: MLP1 + vv + vs (1 edge/thread) ============================
// smem: sW1[160] | sW2a[16*192]  (cols: [0,144)=orig 288..432 (vs), [144,192)=orig 528..576 (vv); both *CV1*0.25)
__global__ __launch_bounds__(128, 3) void edge_a1_kernel(
    const float* __restrict__ hn, const float* __restrict__ he,
    const int* __restrict__ esrc, const int* __restrict__ edst,
    const float* __restrict__ evec, const float* __restrict__ emb,
    const float* __restrict__ fcW1, const float* __restrict__ fcW2, int E)
{
    const float SQ3f    = 1.7320508075688772f;
    const float INVSQ3f = 0.57735026918962576f;
    const float RS10    = 0.31622776601683794f;
    const float CV1     = 0.20412414523193150f;   // 1/sqrt(24)

    __shared__ __align__(16) float sW1[160];
    __shared__ __align__(16) float sW2a[16*192];
    {
        const float4* g1 = (const float4*)fcW1;
        float4* d1 = (float4*)sW1;
        for (int t = threadIdx.x; t < 40; t += 128) {
            float4 a = g1[t]; d1[t] = make_float4(a.x*RS10, a.y*RS10, a.z*RS10, a.w*RS10);
        }
        const float sV = CV1 * 0.25f;
        float4* d2 = (float4*)sW2a;
        for (int t = threadIdx.x; t < 16*48; t += 128) {
            int k = t / 48, q = t % 48;
            int oc = (q < 36) ? (288 + 4*q) : (528 + 4*(q - 36));
            float4 a = *(const float4*)(fcW2 + k*576 + oc);
            d2[t] = make_float4(a.x*sV, a.y*sV, a.z*sV, a.w*sV);
        }
    }
    __syncthreads();

    int e = blockIdx.x*128 + threadIdx.x;
    if (e >= E) return;

    // ---- gather vector parts only ----
    int srcI = esrc[e], dstI = edst[e];
    float vf[36];
    {
        const float4* p = (const float4*)(he + (size_t)e*20);
        const float4* ps = (const float4*)(hn + (size_t)srcI*20);
        const float4* pd = (const float4*)(hn + (size_t)dstI*20);
        float4 a2 = p[2],  a3 = p[3],  a4 = p[4];
        float4 b2 = ps[2], b3 = ps[3], b4 = ps[4];
        float4 c2 = pd[2], c3 = pd[3], c4 = pd[4];
        vf[0]=a2.x; vf[1]=a2.y; vf[2]=a2.z; vf[3]=a2.w;
        vf[4]=a3.x; vf[5]=a3.y; vf[6]=a3.z; vf[7]=a3.w;
        vf[8]=a4.x; vf[9]=a4.y; vf[10]=a4.z; vf[11]=a4.w;
        vf[12]=b2.x; vf[13]=b2.y; vf[14]=b2.z; vf[15]=b2.w;
        vf[16]=b3.x; vf[17]=b3.y; vf[18]=b3.z; vf[19]=b3.w;
        vf[20]=b4.x; vf[21]=b4.y; vf[22]=b4.z; vf[23]=b4.w;
        vf[24]=c2.x; vf[25]=c2.y; vf[26]=c2.z; vf[27]=c2.w;
        vf[28]=c3.x; vf[29]=c3.y; vf[30]=c3.z; vf[31]=c3.w;
        vf[32]=c4.x; vf[33]=c4.y; vf[34]=c4.z; vf[35]=c4.w;
    }

    float sh1[3];
    {
        float ex = evec[e*3+0], ey = evec[e*3+1], ez = evec[e*3+2];
        float nn = sqrtf(ex*ex + ey*ey + ez*ez) + 1e-12f;
        float f = SQ3f / nn;
        sh1[0] = ex*f; sh1[1] = ey*f; sh1[2] = ez*f;
    }
    float dots[12];
#pragma unroll
    for (int i = 0; i < 12; i++)
        dots[i] = (vf[i*3+0]*sh1[0] + vf[i*3+1]*sh1[1] + vf[i*3+2]*sh1[2]) * INVSQ3f;

    // ---- h1 = relu(emb @ fcW1/sqrt(10)) ----
    float h1f[16];
    {
        float embr[10];
        const float2* pe2 = (const float2*)(emb + (size_t)e*10);
#pragma unroll
        for (int j = 0; j < 5; j++) { float2 t = pe2[j]; embr[2*j] = t.x; embr[2*j+1] = t.y; }
        const ulonglong2* W = (const ulonglong2*)sW1;
        u64 acc[8];
#pragma unroll
        for (int p = 0; p < 8; p++) acc[p] = 0ull;
#pragma unroll
        for (int j = 0; j < 10; j++) {
            u64 ej = pack2(embr[j]);
#pragma unroll
            for (int g = 0; g < 4; g++) {
                ulonglong2 w = W[j*4+g];
                acc[2*g]   = fma2(ej, w.x, acc[2*g]);
                acc[2*g+1] = fma2(ej, w.y, acc[2*g+1]);
            }
        }
#pragma unroll
        for (int p = 0; p < 8; p++) {
            float2 f = unpack2(acc[p]);
            h1f[2*p]   = fmaxf(f.x, 0.f);
            h1f[2*p+1] = fmaxf(f.y, 0.f);
        }
    }

    const ulonglong2* W2a = (const ulonglong2*)sW2a;   // 48 chunks per k-row

    // ---- vv: chunks 36 + i (unrolled; consumes vf) ----
    u64 a1p[2][3];
#pragma unroll
    for (int c = 0; c < 3; c++) { a1p[0][c] = 0ull; a1p[1][c] = 0ull; }
#pragma unroll
    for (int i = 0; i < 12; i++) {
        u64 aA = 0ull, aB = 0ull;
#pragma unroll
        for (int k = 0; k < 16; k++) {
            u64 hk = pack2(h1f[k]);
            ulonglong2 w = W2a[k*48 + 36 + i];
            aA = fma2(hk, w.x, aA);
            aB = fma2(hk, w.y, aB);
        }
#pragma unroll
        for (int c = 0; c < 3; c++) {
            u64 vc2 = pack2(vf[i*3+c]);
            a1p[0][c] = fma2(vc2, aA, a1p[0][c]);
            a1p[1][c] = fma2(vc2, aB, a1p[1][c]);
        }
    }

    // ---- vs: chunks i*3 + g (rolled; consumes dots) ----
    u64 a0vp[6];
#pragma unroll
    for (int p = 0; p < 6; p++) a0vp[p] = 0ull;
#pragma unroll 1
    for (int i = 0; i < 12; i += 2) {
        u64 da = pack2(dots[i]);
        u64 db = pack2(dots[i+1]);
        const ulonglong2* Wb = W2a + i*3;
#pragma unroll
        for (int g = 0; g < 3; g++) {
            u64 aA = 0ull, aB = 0ull, bA = 0ull, bB = 0ull;
#pragma unroll
            for (int k = 0; k < 16; k++) {
                u64 hk = pack2(h1f[k]);
                ulonglong2 wa = Wb[k*48 + g];
                ulonglong2 wb = Wb[k*48 + 3 + g];
                aA = fma2(hk, wa.x, aA);
                aB = fma2(hk, wa.y, aB);
                bA = fma2(hk, wb.x, bA);
                bB = fma2(hk, wb.y, bB);
            }
            a0vp[2*g]   = fma2(da, aA, a0vp[2*g]);
            a0vp[2*g+1] = fma2(da, aB, a0vp[2*g+1]);
            a0vp[2*g]   = fma2(db, bA, a0vp[2*g]);
            a0vp[2*g+1] = fma2(db, bB, a0vp[2*g+1]);
        }
    }

    // ---- store mid: h1[16] | a0v[12] | a1[12] ----
    float mid[40];
#pragma unroll
    for (int k = 0; k < 16; k++) mid[k] = h1f[k];
#pragma unroll
    for (int p = 0; p < 6; p++) {
        float2 f = unpack2(a0vp[p]);
        mid[16 + 2*p] = f.x; mid[16 + 2*p + 1] = f.y;
    }
#pragma unroll
    for (int c = 0; c < 3; c++) {
        float2 f0 = unpack2(a1p[0][c]);
        float2 f1 = unpack2(a1p[1][c]);
        mid[28 + 0*3 + c] = f0.x;
        mid[28 + 1*3 + c] = f0.y;
        mid[28 + 2*3 + c] = f1.x;
        mid[28 + 3*3 + c] = f1.y;
    }
    {
        float4* mp = (float4*)(g_mid + (size_t)e*40);
        const float4* sp = (const float4*)mid;
#pragma unroll
        for (int t = 0; t < 10; t++) mp[t] = sp[t];
    }
}

// ============================ Kernel A2: ss + sv (2 edges/thread) + gating ============================
// dyn smem: sW2b2[16*384] floats (cols: [0,288)=orig 0..288 (ss), [288,384)=orig 432..528 (sv); both *CS1*0.25)
//           then scratch u64[128*24] (s pairs, warp-blocked)
#define A2_SMEM_BYTES (16*384*4 + 128*24*8)

__global__ __launch_bounds__(128, 3) void edge_a2_kernel(
    const float* __restrict__ hn, const float* __restrict__ he,
    const int* __restrict__ esrc, const int* __restrict__ edst,
    const float* __restrict__ evec,
    const float* __restrict__ fcW2, int E)
{
    const float SQ3f = 1.7320508075688772f;
    const float CS1  = 0.14433756729740645f;   // 1/sqrt(48)

    extern __shared__ __align__(16) float smemA2[];
    float* sW2b2 = smemA2;
    u64*   scrU  = (u64*)(smemA2 + 16*384);

    {
        const float sS = CS1 * 0.25f;
        float4* d2 = (float4*)sW2b2;
        for (int t = threadIdx.x; t < 16*96; t += 128) {
            int k = t / 96, q = t % 96;
            int oc = (q < 72) ? (4*q) : (432 + 4*(q - 72));
            float4 a = *(const float4*)(fcW2 + k*576 + oc);
            d2[t] = make_float4(a.x*sS, a.y*sS, a.z*sS, a.w*sS);
        }
    }
    __syncthreads();

    int tid  = threadIdx.x;
    int warp = tid >> 5;
    int lane = tid & 31;
    int base = blockIdx.x * 256;
    int e0 = base + tid;
    if (e0 >= E) return;
    int e1 = base + 128 + tid;
    bool v1 = (e1 < E);
    int e1c = v1 ? e1 : e0;

    u64* myU = scrU + (size_t)warp*24*32 + lane;   // slot s -> myU[s*32], half j -> float j

    const ulonglong2* W2b2 = (const ulonglong2*)sW2b2;  // 96 chunks per k-row

    float h1f[2][16];

    // ---- per-edge: gather s -> scratch pairs; load h1 ----
#pragma unroll
    for (int j = 0; j < 2; j++) {
        int e = j ? e1c : e0;
        int srcI = esrc[e], dstI = edst[e];
        {
            const float4* p = (const float4*)(he + (size_t)e*20);
            const float4* ps = (const float4*)(hn + (size_t)srcI*20);
            const float4* pd = (const float4*)(hn + (size_t)dstI*20);
            float4 a0 = p[0],  a1 = p[1];
            float4 b0 = ps[0], b1 = ps[1];
            float4 c0 = pd[0], c1 = pd[1];
            ((float*)(myU + 0*32))[j] = a0.x; ((float*)(myU + 1*32))[j] = a0.y;
            ((float*)(myU + 2*32))[j] = a0.z; ((float*)(myU + 3*32))[j] = a0.w;
            ((float*)(myU + 4*32))[j] = a1.x; ((float*)(myU + 5*32))[j] = a1.y;
            ((float*)(myU + 6*32))[j] = a1.z; ((float*)(myU + 7*32))[j] = a1.w;
            ((float*)(myU + 8*32))[j] = b0.x; ((float*)(myU + 9*32))[j] = b0.y;
            ((float*)(myU + 10*32))[j] = b0.z; ((float*)(myU + 11*32))[j] = b0.w;
            ((float*)(myU + 12*32))[j] = b1.x; ((float*)(myU + 13*32))[j] = b1.y;
            ((float*)(myU + 14*32))[j] = b1.z; ((float*)(myU + 15*32))[j] = b1.w;
            ((float*)(myU + 16*32))[j] = c0.x; ((float*)(myU + 17*32))[j] = c0.y;
            ((float*)(myU + 18*32))[j] = c0.z; ((float*)(myU + 19*32))[j] = c0.w;
            ((float*)(myU + 20*32))[j] = c1.x; ((float*)(myU + 21*32))[j] = c1.y;
            ((float*)(myU + 22*32))[j] = c1.z; ((float*)(myU + 23*32))[j] = c1.w;
        }
        {
            const float4* mp = (const float4*)(g_mid + (size_t)e*40);
            float4 h0 = mp[0], h1v = mp[1], h2v = mp[2], h3 = mp[3];
            h1f[j][0]=h0.x;  h1f[j][1]=h0.y;  h1f[j][2]=h0.z;  h1f[j][3]=h0.w;
            h1f[j][4]=h1v.x; h1f[j][5]=h1v.y; h1f[j][6]=h1v.z; h1f[j][7]=h1v.w;
            h1f[j][8]=h2v.x; h1f[j][9]=h2v.y; h1f[j][10]=h2v.z; h1f[j][11]=h2v.w;
            h1f[j][12]=h3.x; h1f[j][13]=h3.y; h1f[j][14]=h3.z; h1f[j][15]=h3.w;
        }
    }

    // ---- ss: chunks i*3+g, weights shared by both edges ----
    u64 a0p[2][6];
#pragma unroll
    for (int p = 0; p < 6; p++) { a0p[0][p] = 0ull; a0p[1][p] = 0ull; }
#pragma unroll 1
    for (int i = 0; i < 24; i++) {
        float2 sf = unpack2(myU[i*32]);
        u64 s0 = pack2(sf.x);
        u64 s1 = pack2(sf.y);
        const ulonglong2* Wb = W2b2 + i*3;
#pragma unroll
        for (int g = 0; g < 3; g++) {
            u64 aA0 = 0ull, aB0 = 0ull, aA1 = 0ull, aB1 = 0ull;
#pragma unroll
            for (int k = 0; k < 16; k++) {
                u64 hk0 = pack2(h1f[0][k]);
                u64 hk1 = pack2(h1f[1][k]);
                ulonglong2 w = Wb[k*96 + g];
                aA0 = fma2(hk0, w.x, aA0);
                aB0 = fma2(hk0, w.y, aB0);
                aA1 = fma2(hk1, w.x, aA1);
                aB1 = fma2(hk1, w.y, aB1);
            }
            a0p[0][2*g]   = fma2(s0, aA0, a0p[0][2*g]);
            a0p[0][2*g+1] = fma2(s0, aB0, a0p[0][2*g+1]);
            a0p[1][2*g]   = fma2(s1, aA1, a0p[1][2*g]);
            a0p[1][2*g+1] = fma2(s1, aB1, a0p[1][2*g+1]);
        }
    }

    // ---- sv: chunks 72 + i ----
    u64 asvp[2][2];
    asvp[0][0] = 0ull; asvp[0][1] = 0ull; asvp[1][0] = 0ull; asvp[1][1] = 0ull;
#pragma unroll 1
    for (int i = 0; i < 24; i++) {
        u64 aA0 = 0ull, aB0 = 0ull, aA1 = 0ull, aB1 = 0ull;
        const ulonglong2* Wv = W2b2 + 72 + i;
#pragma unroll
        for (int k = 0; k < 16; k++) {
            u64 hk0 = pack2(h1f[0][k]);
            u64 hk1 = pack2(h1f[1][k]);
            ulonglong2 w = Wv[k*96];
            aA0 = fma2(hk0, w.x, aA0);
            aB0 = fma2(hk0, w.y, aB0);
            aA1 = fma2(hk1, w.x, aA1);
            aB1 = fma2(hk1, w.y, aB1);
        }
        float2 sf = unpack2(myU[i*32]);
        u64 s0 = pack2(sf.x);
        u64 s1 = pack2(sf.y);
        asvp[0][0] = fma2(s0, aA0, asvp[0][0]);
        asvp[0][1] = fma2(s0, aB0, asvp[0][1]);
        asvp[1][0] = fma2(s1, aA1, asvp[1][0]);
        asvp[1][1] = fma2(s1, aB1, asvp[1][1]);
    }

    // ---- epilogue per edge: combine with A1 partials, gate, write g_tmp ----
#pragma unroll
    for (int j = 0; j < 2; j++) {
        if (j == 1 && !v1) break;
        int e = j ? e1 : e0;
        float sh[3];
        {
            float ex = evec[e*3+0], ey = evec[e*3+1], ez = evec[e*3+2];
            float nn = sqrtf(ex*ex + ey*ey + ez*ez) + 1e-12f;
            float f = SQ3f / nn;
            sh[0] = ex*f; sh[1] = ey*f; sh[2] = ez*f;
        }
        // load partials: a0v[12] at mid+16, a1[12] at mid+28
        float pv[12], pa[12];
        {
            const float4* mp = (const float4*)(g_mid + (size_t)e*40 + 16);
            float4 m0 = mp[0], m1 = mp[1], m2 = mp[2];
            pv[0]=m0.x; pv[1]=m0.y; pv[2]=m0.z; pv[3]=m0.w;
            pv[4]=m1.x; pv[5]=m1.y; pv[6]=m1.z; pv[7]=m1.w;
            pv[8]=m2.x; pv[9]=m2.y; pv[10]=m2.z; pv[11]=m2.w;
            const float4* mq = (const float4*)(g_mid + (size_t)e*40 + 28);
            float4 n0 = mq[0], n1 = mq[1], n2 = mq[2];
            pa[0]=n0.x; pa[1]=n0.y; pa[2]=n0.z; pa[3]=n0.w;
            pa[4]=n1.x; pa[5]=n1.y; pa[6]=n1.z; pa[7]=n1.w;
            pa[8]=n2.x; pa[9]=n2.y; pa[10]=n2.z; pa[11]=n2.w;
        }
        float outr[20];
        float a0[12], asv[4];
#pragma unroll
        for (int p = 0; p < 6; p++) {
            float2 f = unpack2(a0p[j][p]);
            a0[2*p]   = f.x + pv[2*p];
            a0[2*p+1] = f.y + pv[2*p+1];
        }
        {
            float2 f0 = unpack2(asvp[j][0]); float2 f1 = unpack2(asvp[j][1]);
            asv[0] = f0.x; asv[1] = f0.y; asv[2] = f1.x; asv[3] = f1.y;
        }
#pragma unroll
        for (int o = 0; o < 8; o++) outr[o] = fmaxf(a0[o], 0.f);
#pragma unroll
        for (int o = 0; o < 4; o++) {
            float gate = fmaxf(a0[8+o], 0.f);
#pragma unroll
            for (int c = 0; c < 3; c++)
                outr[8 + o*3 + c] = (asv[o]*sh[c] + pa[o*3+c]) * gate;
        }
        float4* tp = (float4*)(g_tmp + (size_t)e*20);
        const float4* sp = (const float4*)outr;
#pragma unroll
        for (int t = 0; t < 5; t++) tp[t] = sp[t];
    }
}

// ============================ Kernel B: MLP2 + TP2 + epilogue (unchanged champion) ============================
__global__ __launch_bounds__(128, 4) void edge_tp2_kernel(
    const float* __restrict__ he,
    const int* __restrict__ edst, const float* __restrict__ evec,
    const float* __restrict__ emb, const float* __restrict__ enorm,
    const float* __restrict__ fc2W1, const float* __restrict__ fc2W2,
    float* __restrict__ out_he, int E)
{
    const float SQ3f    = 1.7320508075688772f;
    const float INVSQ3f = 0.57735026918962576f;
    const float RS10    = 0.31622776601683794f;
    const float CS2     = 0.25f;
    const float CV2     = 0.35355339059327379f;

    __shared__ __align__(16) float sW1b[160];
    __shared__ __align__(16) float sW2b[2304];
    {
        const float4* g1b = (const float4*)fc2W1;
        float4* d1b = (float4*)sW1b;
        for (int t = threadIdx.x; t < 40; t += 128) {
            float4 b = g1b[t]; d1b[t] = make_float4(b.x*RS10, b.y*RS10, b.z*RS10, b.w*RS10);
        }
        const float4* g2b = (const float4*)fc2W2;
        float4* d2b = (float4*)sW2b;
        const float sS = CS2 * 0.25f, sV = CV2 * 0.25f;
        for (int t = threadIdx.x; t < 576; t += 128) {
            int c0 = (t*4) % 144;
            float sc = (c0 < 64) ? sS : (c0 < 96) ? sV : (c0 < 128) ? sS : sV;
            float4 a = g2b[t]; d2b[t] = make_float4(a.x*sc, a.y*sc, a.z*sc, a.w*sc);
        }
    }
    __syncthreads();

    int e = blockIdx.x*128 + threadIdx.x;
    if (e >= E) return;

    float ts[8], tv[12];
    {
        float4 r[5];
        const float4* tp = (const float4*)(g_tmp + (size_t)e*20);
#pragma unroll
        for (int i = 0; i < 5; i++) r[i] = tp[i];
        const float* f = (const float*)r;
#pragma unroll
        for (int j = 0; j < 8; j++) ts[j] = f[j];
#pragma unroll
        for (int j = 0; j < 12; j++) tv[j] = f[8+j];
    }

    float sh1[3];
    {
        float ex = evec[e*3+0], ey = evec[e*3+1], ez = evec[e*3+2];
        float nn = sqrtf(ex*ex + ey*ey + ez*ez) + 1e-12f;
        float f = SQ3f / nn;
        sh1[0] = ex*f; sh1[1] = ey*f; sh1[2] = ez*f;
    }
    float dt[4];
#pragma unroll
    for (int i = 0; i < 4; i++)
        dt[i] = (tv[i*3+0]*sh1[0] + tv[i*3+1]*sh1[1] + tv[i*3+2]*sh1[2]) * INVSQ3f;

    u64 h2p[16];
    {
        float embr[10];
        const float2* pe2 = (const float2*)(emb + (size_t)e*10);
#pragma unroll
        for (int j = 0; j < 5; j++) { float2 t = pe2[j]; embr[2*j] = t.x; embr[2*j+1] = t.y; }
        const ulonglong2* W = (const ulonglong2*)sW1b;
        u64 acc[8];
#pragma unroll
        for (int p = 0; p < 8; p++) acc[p] = 0ull;
#pragma unroll
        for (int j = 0; j < 10; j++) {
            u64 ej = pack2(embr[j]);
#pragma unroll
            for (int g = 0; g < 4; g++) {
                ulonglong2 w = W[j*4+g];
                acc[2*g]   = fma2(ej, w.x, acc[2*g]);
                acc[2*g+1] = fma2(ej, w.y, acc[2*g+1]);
            }
        }
#pragma unroll
        for (int p = 0; p < 8; p++) {
            float2 f = unpack2(acc[p]);
            h2p[2*p]   = pack2(fmaxf(f.x, 0.f));
            h2p[2*p+1] = pack2(fmaxf(f.y, 0.f));
        }
    }

    const ulonglong2* W2b = (const ulonglong2*)sW2b;  // 36 chunks per k-row
    u64 b0p[4], bsvp[2], b1p[2][3];
#pragma unroll
    for (int p = 0; p < 4; p++) b0p[p] = 0ull;
    bsvp[0] = 0ull; bsvp[1] = 0ull;
#pragma unroll
    for (int c = 0; c < 3; c++) { b1p[0][c] = 0ull; b1p[1][c] = 0ull; }

#pragma unroll
    for (int i = 0; i < 8; i++) {
        u64 si2 = pack2(ts[i]);
#pragma unroll
        for (int g = 0; g < 2; g++) {
            u64 aA = 0ull, aB = 0ull;
#pragma unroll
            for (int k = 0; k < 16; k++) {
                ulonglong2 w = W2b[k*36 + i*2 + g];
                aA = fma2(h2p[k], w.x, aA);
                aB = fma2(h2p[k], w.y, aB);
            }
            b0p[2*g]   = fma2(si2, aA, b0p[2*g]);
            b0p[2*g+1] = fma2(si2, aB, b0p[2*g+1]);
        }
    }
#pragma unroll
    for (int i = 0; i < 4; i++) {
        u64 di2 = pack2(dt[i]);
#pragma unroll
        for (int g = 0; g < 2; g++) {
            u64 aA = 0ull, aB = 0ull;
#pragma unroll
            for (int k = 0; k < 16; k++) {
                ulonglong2 w = W2b[k*36 + 16 + i*2 + g];
                aA = fma2(h2p[k], w.x, aA);
                aB = fma2(h2p[k], w.y, aB);
            }
            b0p[2*g]   = fma2(di2, aA, b0p[2*g]);
            b0p[2*g+1] = fma2(di2, aB, b0p[2*g+1]);
        }
    }
#pragma unroll
    for (int i = 0; i < 8; i++) {
        u64 aA = 0ull, aB = 0ull;
#pragma unroll
        for (int k = 0; k < 16; k++) {
            ulonglong2 w = W2b[k*36 + 24 + i];
            aA = fma2(h2p[k], w.x, aA);
            aB = fma2(h2p[k], w.y, aB);
        }
        u64 si2 = pack2(ts[i]);
        bsvp[0] = fma2(si2, aA, bsvp[0]);
        bsvp[1] = fma2(si2, aB, bsvp[1]);
    }
#pragma unroll
    for (int i = 0; i < 4; i++) {
        u64 aA = 0ull, aB = 0ull;
#pragma unroll
        for (int k = 0; k < 16; k++) {
            ulonglong2 w = W2b[k*36 + 32 + i];
            aA = fma2(h2p[k], w.x, aA);
            aB = fma2(h2p[k], w.y, aB);
        }
#pragma unroll
        for (int c = 0; c < 3; c++) {
            u64 vc2 = pack2(tv[i*3+c]);
            b1p[0][c] = fma2(vc2, aA, b1p[0][c]);
            b1p[1][c] = fma2(vc2, aB, b1p[1][c]);
        }
    }

    float b0[8], bsv[4], b1[4][3];
#pragma unroll
    for (int p = 0; p < 4; p++) {
        float2 f = unpack2(b0p[p]);
        b0[2*p] = f.x; b0[2*p+1] = f.y;
    }
    {
        float2 f0 = unpack2(bsvp[0]); float2 f1 = unpack2(bsvp[1]);
        bsv[0] = f0.x; bsv[1] = f0.y; bsv[2] = f1.x; bsv[3] = f1.y;
    }
#pragma unroll
    for (int c = 0; c < 3; c++) {
        float2 f0 = unpack2(b1p[0][c]); float2 f1 = unpack2(b1p[1][c]);
        b1[0][c] = f0.x; b1[1][c] = f0.y; b1[2][c] = f1.x; b1[3][c] = f1.y;
    }

    float hnew[20];
    {
        float4 r[5];
        const float4* p = (const float4*)(he + (size_t)e*20);
#pragma unroll
        for (int i = 0; i < 5; i++) r[i] = p[i];
        const float* re = (const float*)r;
#pragma unroll
        for (int j = 0; j < 8; j++) hnew[j] = re[j] + b0[j];
#pragma unroll
        for (int o = 0; o < 4; o++)
#pragma unroll
            for (int c = 0; c < 3; c++)
                hnew[8 + o*3 + c] = re[8+o*3+c] + (bsv[o]*sh1[c] + b1[o][c]);
    }

    {
        float4* op = (float4*)(out_he + (size_t)e*20);
        const float4* hp = (const float4*)hnew;
#pragma unroll
        for (int t = 0; t < 5; t++) op[t] = hp[t];
    }
    int dstI = edst[e];
    float nw = enorm[e];
    float* nf = &g_nodeftr[(size_t)dstI*20];
#pragma unroll
    for (int t = 0; t < 5; t++)
        red4(nf + t*4, hnew[t*4]*nw, hnew[t*4+1]*nw, hnew[t*4+2]*nw, hnew[t*4+3]*nw);
}

// ============================ node kernel (also re-zeroes g_nodeftr) ============================
__global__ __launch_bounds__(32) void node_kernel(
    const float* __restrict__ hn,
    const float* __restrict__ WgS, const float* __restrict__ WgV,
    const float* __restrict__ WoS, const float* __restrict__ WoV,
    float* __restrict__ out_hn, int N)
{
    const float RS8 = 0.35355339059327379f;
    int n = blockIdx.x*32 + threadIdx.x;
    if (n >= N) return;

    float cs[16], cv[8][3];
    const float* ph = hn + (size_t)n*20;
    float* pf = g_nodeftr + (size_t)n*20;
#pragma unroll
    for (int j = 0; j < 8; j++) { cs[j] = ph[j]; cs[8+j] = pf[j]; }
#pragma unroll
    for (int i = 0; i < 4; i++)
#pragma unroll
        for (int c = 0; c < 3; c++) { cv[i][c] = ph[8+i*3+c]; cv[4+i][c] = pf[8+i*3+c]; }

    {
        float4 z4 = make_float4(0.f, 0.f, 0.f, 0.f);
        float4* pz = (float4*)pf;
#pragma unroll
        for (int t = 0; t < 5; t++) pz[t] = z4;
    }

    float gl[12];
#pragma unroll
    for (int o = 0; o < 12; o++) {
        float a = 0.f;
#pragma unroll
        for (int i = 0; i < 16; i++) a = fmaf(cs[i], __ldg(&WgS[i*12+o]), a);
        gl[o] = a * 0.25f;
    }
    float vl[4][3];
#pragma unroll
    for (int o = 0; o < 4; o++)
#pragma unroll
        for (int c = 0; c < 3; c++) {
            float a = 0.f;
#pragma unroll
            for (int i = 0; i < 8; i++) a = fmaf(cv[i][c], __ldg(&WgV[i*4+o]), a);
            vl[o][c] = a * RS8;
        }

    float ls[8], lg[4];
#pragma unroll
    for (int j = 0; j < 8; j++) ls[j] = fmaxf(gl[j], 0.f);
#pragma unroll
    for (int o = 0; o < 4; o++) lg[o] = fmaxf(gl[8+o], 0.f);

    float lv[4][3];
#pragma unroll
    for (int o = 0; o < 4; o++)
#pragma unroll
        for (int c = 0; c < 3; c++) lv[o][c] = vl[o][c] * lg[o];

    float os_[8];
#pragma unroll
    for (int o = 0; o < 8; o++) {
        float a = 0.f;
#pragma unroll
        for (int i = 0; i < 8; i++) a = fmaf(ls[i], __ldg(&WoS[i*8+o]), a);
        os_[o] = a * RS8;
    }
    float ov[4][3];
#pragma unroll
    for (int o = 0; o < 4; o++)
#pragma unroll
        for (int c = 0; c < 3; c++) {
            float a = 0.f;
#pragma unroll
            for (int i = 0; i < 4; i++) a = fmaf(lv[i][c], __ldg(&WoV[i*4+o]), a);
            ov[o][c] = a * 0.5f;
        }

    float* po = out_hn + (size_t)n*20;
#pragma unroll
    for (int j = 0; j < 8; j++) po[j] = ph[j] + os_[j];
#pragma unroll
    for (int o = 0; o < 4; o++)
#pragma unroll
        for (int c = 0; c < 3; c++) po[8+o*3+c] = ph[8+o*3+c] + ov[o][c];
}

extern "C" void kernel_launch(void* const* d_in, const int* in_sizes, int n_in,
                              void* d_out, int out_size) {
    const float* hn    = (const float*)d_in[0];
    const float* he    = (const float*)d_in[1];
    const int*   esrc  = (const int*)d_in[2];
    const int*   edst  = (const int*)d_in[3];
    const float* evec  = (const float*)d_in[4];
    const float* emb   = (const float*)d_in[5];
    const float* enorm = (const float*)d_in[6];
    const float* fcW1  = (const float*)d_in[8];
    const float* fcW2  = (const float*)d_in[9];
    const float* fc2W1 = (const float*)d_in[10];
    const float* fc2W2 = (const float*)d_in[11];
    const float* WgS   = (const float*)d_in[12];
    const float* WgV   = (const float*)d_in[13];
    const float* WoS   = (const float*)d_in[14];
    const float* WoV   = (const float*)d_in[15];

    int N = in_sizes[0] / 20;
    int E = in_sizes[1] / 20;

    float* out    = (float*)d_out;
    float* out_hn = out;                      // (N,20) first
    float* out_he = out + (size_t)N * 20;     // (E,20) second

    cudaFuncSetAttribute(edge_a2_kernel,
                         cudaFuncAttributeMaxDynamicSharedMemorySize, A2_SMEM_BYTES);

    edge_a1_kernel<<<(E + 127)/128, 128>>>(hn, he, esrc, edst, evec, emb, fcW1, fcW2, E);
    edge_a2_kernel<<<(E + 255)/256, 128, A2_SMEM_BYTES>>>(hn, he, esrc, edst, evec, fcW2, E);
    edge_tp2_kernel<<<(E + 127)/128, 128>>>(he, edst, evec, emb, enorm, fc2W1, fc2W2, out_he, E);
    node_kernel<<<(N + 31)/32, 32>>>(hn, WgS, WgV, WoS, WoV, out_hn, N);
}